// round 4
// baseline (speedup 1.0000x reference)
#include <cuda_runtime.h>
#include <math.h>

#define N_NODES 50000
#define N_EDGES 640000
#define SF  128
#define MAX_IT 10
#define THRC 0.01f

// ---------------- device scratch ----------------
__device__ float g_cur [N_NODES * SF];
__device__ float g_old [N_NODES * SF];
__device__ float g_aggs[N_NODES * SF];
__device__ float g_aggn[N_NODES * SF];
__device__ float g_agga[N_NODES * 64];
__device__ float g_hidden[N_NODES * 512];

__device__ int   g_cnt_adj[N_NODES];
__device__ int   g_rp_adj [N_NODES + 1];
__device__ int   g_cursor_adj[N_NODES];
__device__ int   g_csr_src[N_EDGES];
__device__ float g_csr_val[N_EDGES];

__device__ int   g_cnt_an[N_NODES];
__device__ int   g_rp_an [N_NODES + 1];
__device__ int   g_cursor_an[N_NODES];
__device__ int   g_csr2_eid[N_EDGES];
__device__ float g_csr2_val[N_EDGES];

__device__ int g_cont;
__device__ int g_done;

// ---------------- init ----------------
__global__ void k_init(const float* __restrict__ state_init) {
    int i = blockIdx.x * blockDim.x + threadIdx.x;
    if (i < N_NODES * SF) { g_cur[i] = state_init[i]; g_old[i] = 1.0f; }
    if (i < N_NODES) {
        g_cnt_adj[i] = 0; g_cnt_an[i] = 0;
        g_cursor_adj[i] = 0; g_cursor_an[i] = 0;
    }
    if (i == 0) { g_done = 0; g_cont = 0; }
}

__global__ void k_hist(const int* __restrict__ adj_dst, const int* __restrict__ an_dst) {
    int e = blockIdx.x * blockDim.x + threadIdx.x;
    if (e >= N_EDGES) return;
    atomicAdd(&g_cnt_adj[adj_dst[e]], 1);
    atomicAdd(&g_cnt_an[an_dst[e]], 1);
}

__global__ void k_scan() {
    const int* cnt = blockIdx.x ? g_cnt_an : g_cnt_adj;
    int* rp        = blockIdx.x ? g_rp_an  : g_rp_adj;
    __shared__ int sums[1024];
    const int CHUNK = (N_NODES + 1023) / 1024;
    int t = threadIdx.x;
    int begin = t * CHUNK;
    int end = begin + CHUNK; if (end > N_NODES) end = N_NODES;
    int s = 0;
    for (int i = begin; i < end; i++) s += cnt[i];
    sums[t] = s;
    __syncthreads();
    for (int off = 1; off < 1024; off <<= 1) {
        int v = (t >= off) ? sums[t - off] : 0;
        __syncthreads();
        sums[t] += v;
        __syncthreads();
    }
    int run = sums[t] - s;
    for (int i = begin; i < end; i++) { rp[i] = run; run += cnt[i]; }
    if (t == 1023) rp[N_NODES] = sums[1023];
}

__global__ void k_scatter(const int* __restrict__ adj_src, const int* __restrict__ adj_dst,
                          const float* __restrict__ adj_vals,
                          const int* __restrict__ an_dst, const float* __restrict__ an_vals) {
    int e = blockIdx.x * blockDim.x + threadIdx.x;
    if (e >= N_EDGES) return;
    {
        int d = adj_dst[e];
        int p = atomicAdd(&g_cursor_adj[d], 1);
        int idx = g_rp_adj[d] + p;
        g_csr_src[idx] = adj_src[e];
        g_csr_val[idx] = adj_vals[e];
    }
    {
        int d = an_dst[e];
        int p = atomicAdd(&g_cursor_an[d], 1);
        int idx = g_rp_an[d] + p;
        g_csr2_eid[idx] = e;
        g_csr2_val[idx] = an_vals[e];
    }
}

// ---------------- SpMM: one warp per destination row ----------------
template<bool GUARD>
__global__ void k_spmm(const float* __restrict__ dense, float* __restrict__ out) {
    if (GUARD && g_cont == 0) return;
    int w = (blockIdx.x * blockDim.x + threadIdx.x) >> 5;
    int lane = threadIdx.x & 31;
    if (w >= N_NODES) return;
    int i0 = g_rp_adj[w], i1 = g_rp_adj[w + 1];
    float4 acc = make_float4(0.f, 0.f, 0.f, 0.f);
    for (int i = i0; i < i1; i++) {
        int src = g_csr_src[i];
        float v = g_csr_val[i];
        float4 x = *reinterpret_cast<const float4*>(dense + (size_t)src * 128 + lane * 4);
        acc.x += v * x.x; acc.y += v * x.y; acc.z += v * x.z; acc.w += v * x.w;
    }
    *reinterpret_cast<float4*>(out + (size_t)w * 128 + lane * 4) = acc;
}

__global__ void k_agg_arcs(const float* __restrict__ arcs) {
    int w = (blockIdx.x * blockDim.x + threadIdx.x) >> 5;
    int lane = threadIdx.x & 31;
    if (w >= N_NODES) return;
    int i0 = g_rp_an[w], i1 = g_rp_an[w + 1];
    float ax = 0.f, ay = 0.f;
    for (int i = i0; i < i1; i++) {
        int e = g_csr2_eid[i];
        float v = g_csr2_val[i];
        float2 x = *reinterpret_cast<const float2*>(arcs + (size_t)e * 66 + 2 + lane * 2);
        ax += v * x.x; ay += v * x.y;
    }
    float2 o; o.x = ax; o.y = ay;
    *reinterpret_cast<float2*>(g_agga + (size_t)w * 64 + lane * 2) = o;
}

// ---------------- convergence control ----------------
__global__ void k_reset_cont() { g_cont = 0; }
__global__ void k_latch()      { if (g_cont == 0) g_done = 1; }

__global__ void k_dist() {
    if (g_done) return;
    int w = (blockIdx.x * blockDim.x + threadIdx.x) >> 5;
    int lane = threadIdx.x & 31;
    if (w >= N_NODES) return;
    float4 c = *reinterpret_cast<const float4*>(g_cur + (size_t)w * 128 + lane * 4);
    float4 o = *reinterpret_cast<const float4*>(g_old + (size_t)w * 128 + lane * 4);
    float dx = c.x - o.x, dy = c.y - o.y, dz = c.z - o.z, dw = c.w - o.w;
    float d2 = dx * dx + dy * dy + dz * dz + dw * dw;
    float n2 = o.x * o.x + o.y * o.y + o.z * o.z + o.w * o.w;
    #pragma unroll
    for (int off = 16; off > 0; off >>= 1) {
        d2 += __shfl_down_sync(0xffffffffu, d2, off);
        n2 += __shfl_down_sync(0xffffffffu, n2, off);
    }
    if (lane == 0) {
        if (sqrtf(d2) > THRC * sqrtf(n2)) g_cont = 1;
    }
}

// ---------------- double-buffered SGEMM, fused concat + tanh ----------------
// 128x128 tile, 256 threads, 8x8/thread, K-step 8, ping-pong smem.
// AMODE: 0 = plain A0 (stride KTOT); 1 = concat of 5 (KTOT=576); 2 = concat of 2 (KTOT=256)
// EPI: 0 = plain tanh write; 1 = commit Cold<-C then C<-tanh (NTOT=128 state update)
template<int KTOT, int NTOT, int AMODE, bool GUARD, int EPI>
__global__ void __launch_bounds__(256) k_gemm(
    const float* __restrict__ A0, const float* __restrict__ A1,
    const float* __restrict__ A2, const float* __restrict__ A3,
    const float* __restrict__ A4,
    const float* __restrict__ B,  const float* __restrict__ bias,
    float* __restrict__ C, float* __restrict__ Cold)
{
    if (GUARD && g_cont == 0) return;
    __shared__ float As[2][8][128];
    __shared__ float Bs[2][8][132];   // padded stride: avoid LDS bank camping
    const int tid = threadIdx.x;
    const int tx = tid & 15, ty = tid >> 4;
    const int bm = blockIdx.y, bn = blockIdx.x;
    const int rowA = tid >> 1, kA = (tid & 1) * 4;
    const int kB = tid >> 5, nB = (tid & 31) * 4;

    float acc[8][8];
    #pragma unroll
    for (int i = 0; i < 8; i++)
        #pragma unroll
        for (int j = 0; j < 8; j++) acc[i][j] = 0.f;

    const int mA = bm * 128 + rowA;
    const int KT = KTOT / 8;

    auto loadA = [&](int kg) -> float4 {
        float4 av = make_float4(0.f, 0.f, 0.f, 0.f);
        if (mA < N_NODES) {
            const int k = kg + kA;
            const float* p;
            if (AMODE == 0) {
                p = A0 + (size_t)mA * KTOT + k;
            } else if (AMODE == 2) {
                p = (k < 128) ? (A0 + (size_t)mA * 128 + k)
                              : (A1 + (size_t)mA * 128 + (k - 128));
            } else {
                if      (k < 128) p = A0 + (size_t)mA * 128 + k;
                else if (k < 256) p = A1 + (size_t)mA * 128 + (k - 128);
                else if (k < 384) p = A2 + (size_t)mA * 128 + (k - 256);
                else if (k < 512) p = A3 + (size_t)mA * 128 + (k - 384);
                else              p = A4 + (size_t)mA * 64  + (k - 512);
            }
            av = *reinterpret_cast<const float4*>(p);
        }
        return av;
    };
    auto loadB = [&](int kg) -> float4 {
        return *reinterpret_cast<const float4*>(B + (size_t)(kg + kB) * NTOT + bn * 128 + nB);
    };
    auto stage = [&](int buf, float4 av, float4 bv) {
        As[buf][kA + 0][rowA] = av.x;
        As[buf][kA + 1][rowA] = av.y;
        As[buf][kA + 2][rowA] = av.z;
        As[buf][kA + 3][rowA] = av.w;
        *reinterpret_cast<float4*>(&Bs[buf][kB][nB]) = bv;
    };

    {
        float4 av = loadA(0), bv = loadB(0);
        stage(0, av, bv);
    }
    __syncthreads();

    for (int kt = 0; kt < KT; kt++) {
        const int cur = kt & 1, nxt = cur ^ 1;
        float4 av, bv;
        if (kt + 1 < KT) { av = loadA((kt + 1) * 8); bv = loadB((kt + 1) * 8); }

        #pragma unroll
        for (int k = 0; k < 8; k++) {
            float4 a0 = *reinterpret_cast<const float4*>(&As[cur][k][ty * 4]);
            float4 a1 = *reinterpret_cast<const float4*>(&As[cur][k][64 + ty * 4]);
            float4 b0 = *reinterpret_cast<const float4*>(&Bs[cur][k][tx * 4]);
            float4 b1 = *reinterpret_cast<const float4*>(&Bs[cur][k][64 + tx * 4]);
            float a[8] = {a0.x, a0.y, a0.z, a0.w, a1.x, a1.y, a1.z, a1.w};
            float b[8] = {b0.x, b0.y, b0.z, b0.w, b1.x, b1.y, b1.z, b1.w};
            #pragma unroll
            for (int i = 0; i < 8; i++)
                #pragma unroll
                for (int j = 0; j < 8; j++)
                    acc[i][j] += a[i] * b[j];
        }

        if (kt + 1 < KT) {
            stage(nxt, av, bv);
            __syncthreads();
        }
    }

    #pragma unroll
    for (int i = 0; i < 8; i++) {
        int r = (i < 4) ? (ty * 4 + i) : (64 + ty * 4 + (i - 4));
        int m = bm * 128 + r;
        if (m >= N_NODES) continue;
        #pragma unroll
        for (int jh = 0; jh < 2; jh++) {
            int n0 = bn * 128 + jh * 64 + tx * 4;
            float4 o;
            o.x = tanhf(acc[i][jh * 4 + 0] + bias[n0 + 0]);
            o.y = tanhf(acc[i][jh * 4 + 1] + bias[n0 + 1]);
            o.z = tanhf(acc[i][jh * 4 + 2] + bias[n0 + 2]);
            o.w = tanhf(acc[i][jh * 4 + 3] + bias[n0 + 3]);
            if (EPI == 1) {
                float4 cv = *reinterpret_cast<const float4*>(C + (size_t)m * NTOT + n0);
                *reinterpret_cast<float4*>(Cold + (size_t)m * NTOT + n0) = cv;
            }
            *reinterpret_cast<float4*>(C + (size_t)m * NTOT + n0) = o;
        }
    }
}

// ---------------- final projection ----------------
__global__ void k_out(const float* __restrict__ Wo2, const float* __restrict__ bo2,
                      const int* __restrict__ m1, const int* __restrict__ m2,
                      float* __restrict__ out) {
    __shared__ float w[512 * 7];
    int tid = threadIdx.x;
    for (int i = tid; i < 512 * 7; i += 256) w[i] = Wo2[i];
    __syncthreads();
    int warp = tid >> 5, lane = tid & 31;
    int row = blockIdx.x * 8 + warp;
    if (row >= N_NODES) return;
    float acc[7] = {0.f, 0.f, 0.f, 0.f, 0.f, 0.f, 0.f};
    const float* h = g_hidden + (size_t)row * 512;
    for (int k = lane; k < 512; k += 32) {
        float hv = h[k];
        #pragma unroll
        for (int j = 0; j < 7; j++) acc[j] += hv * w[k * 7 + j];
    }
    #pragma unroll
    for (int j = 0; j < 7; j++)
        #pragma unroll
        for (int off = 16; off > 0; off >>= 1)
            acc[j] += __shfl_down_sync(0xffffffffu, acc[j], off);
    if (lane == 0) {
        float msk = (m1[row] != 0 && m2[row] != 0) ? 1.f : 0.f;
        #pragma unroll
        for (int j = 0; j < 7; j++)
            out[(size_t)row * 7 + j] = (acc[j] + bo2[j]) * msk;
    }
}

// ---------------- launcher ----------------
extern "C" void kernel_launch(void* const* d_in, const int* in_sizes, int n_in,
                              void* d_out, int out_size) {
    const float* nodes      = (const float*)d_in[0];
    const float* arcs       = (const float*)d_in[1];
    const int*   smask      = (const int*)d_in[2];
    const int*   omask      = (const int*)d_in[3];
    const int*   adj_src    = (const int*)d_in[4];
    const int*   adj_dst    = (const int*)d_in[5];
    const float* adj_vals   = (const float*)d_in[6];
    const int*   an_dst     = (const int*)d_in[7];
    const float* an_vals    = (const float*)d_in[8];
    const float* state_init = (const float*)d_in[9];
    const float* Ws1        = (const float*)d_in[10];
    const float* bs1        = (const float*)d_in[11];
    const float* Ws2        = (const float*)d_in[12];
    const float* bs2        = (const float*)d_in[13];
    const float* Wo1        = (const float*)d_in[14];
    const float* bo1        = (const float*)d_in[15];
    const float* Wo2        = (const float*)d_in[16];
    const float* bo2        = (const float*)d_in[17];
    float* out = (float*)d_out;

    float *p_cur, *p_old, *p_aggs, *p_aggn, *p_agga, *p_hidden;
    cudaGetSymbolAddress((void**)&p_cur,    g_cur);
    cudaGetSymbolAddress((void**)&p_old,    g_old);
    cudaGetSymbolAddress((void**)&p_aggs,   g_aggs);
    cudaGetSymbolAddress((void**)&p_aggn,   g_aggn);
    cudaGetSymbolAddress((void**)&p_agga,   g_agga);
    cudaGetSymbolAddress((void**)&p_hidden, g_hidden);

    const int MBLK = (N_NODES + 127) / 128;

    k_init<<<(N_NODES * SF + 255) / 256, 256>>>(state_init);
    k_hist<<<(N_EDGES + 255) / 256, 256>>>(adj_dst, an_dst);
    k_scan<<<2, 1024>>>();
    k_scatter<<<(N_EDGES + 255) / 256, 256>>>(adj_src, adj_dst, adj_vals, an_dst, an_vals);
    k_agg_arcs<<<(N_NODES * 32 + 255) / 256, 256>>>(arcs);
    k_spmm<false><<<(N_NODES * 32 + 255) / 256, 256>>>(nodes, p_aggn);

    for (int it = 0; it < MAX_IT; it++) {
        k_reset_cont<<<1, 1>>>();
        k_dist<<<(N_NODES * 32 + 255) / 256, 256>>>();
        k_latch<<<1, 1>>>();
        k_spmm<true><<<(N_NODES * 32 + 255) / 256, 256>>>(p_cur, p_aggs);
        k_gemm<576, 512, 1, true, 0><<<dim3(4, MBLK), 256>>>(
            p_cur, nodes, p_aggs, p_aggn, p_agga, Ws1, bs1, p_hidden, nullptr);
        k_gemm<512, 128, 0, true, 1><<<dim3(1, MBLK), 256>>>(
            p_hidden, nullptr, nullptr, nullptr, nullptr, Ws2, bs2, p_cur, p_old);
    }

    k_gemm<256, 512, 2, false, 0><<<dim3(4, MBLK), 256>>>(
        p_cur, nodes, nullptr, nullptr, nullptr, Wo1, bo1, p_hidden, nullptr);
    k_out<<<(N_NODES + 7) / 8, 256>>>(Wo2, bo2, smask, omask, out);
}

// round 5
// speedup vs baseline: 1.3792x; 1.3792x over previous
#include <cuda_runtime.h>
#include <math.h>
#include <stdint.h>

#define N_NODES 50000
#define N_EDGES 640000
#define SF  128
#define MAX_IT 10
#define THRC 0.01f

// ---------------- device scratch ----------------
__device__ float g_cur [N_NODES * SF];
__device__ float g_old [N_NODES * SF];
__device__ float g_aggs[N_NODES * SF];
__device__ float g_aggn[N_NODES * SF];
__device__ float g_agga[N_NODES * 64];
__device__ float g_hidden[N_NODES * 512];

__device__ int   g_cnt_adj[N_NODES];
__device__ int   g_rp_adj [N_NODES + 1];
__device__ int   g_cursor_adj[N_NODES];
__device__ int   g_csr_src[N_EDGES];
__device__ float g_csr_val[N_EDGES];

__device__ int   g_cnt_an[N_NODES];
__device__ int   g_rp_an [N_NODES + 1];
__device__ int   g_cursor_an[N_NODES];
__device__ int   g_csr2_eid[N_EDGES];
__device__ float g_csr2_val[N_EDGES];

__device__ int g_cont;
__device__ int g_done;

// ---------------- init ----------------
__global__ void k_init(const float* __restrict__ state_init) {
    int i = blockIdx.x * blockDim.x + threadIdx.x;
    if (i < N_NODES * SF) { g_cur[i] = state_init[i]; g_old[i] = 1.0f; }
    if (i < N_NODES) {
        g_cnt_adj[i] = 0; g_cnt_an[i] = 0;
        g_cursor_adj[i] = 0; g_cursor_an[i] = 0;
    }
    if (i == 0) { g_done = 0; g_cont = 0; }
}

__global__ void k_hist(const int* __restrict__ adj_dst, const int* __restrict__ an_dst) {
    int e = blockIdx.x * blockDim.x + threadIdx.x;
    if (e >= N_EDGES) return;
    atomicAdd(&g_cnt_adj[adj_dst[e]], 1);
    atomicAdd(&g_cnt_an[an_dst[e]], 1);
}

__global__ void k_scan() {
    const int* cnt = blockIdx.x ? g_cnt_an : g_cnt_adj;
    int* rp        = blockIdx.x ? g_rp_an  : g_rp_adj;
    __shared__ int sums[1024];
    const int CHUNK = (N_NODES + 1023) / 1024;
    int t = threadIdx.x;
    int begin = t * CHUNK;
    int end = begin + CHUNK; if (end > N_NODES) end = N_NODES;
    int s = 0;
    for (int i = begin; i < end; i++) s += cnt[i];
    sums[t] = s;
    __syncthreads();
    for (int off = 1; off < 1024; off <<= 1) {
        int v = (t >= off) ? sums[t - off] : 0;
        __syncthreads();
        sums[t] += v;
        __syncthreads();
    }
    int run = sums[t] - s;
    for (int i = begin; i < end; i++) { rp[i] = run; run += cnt[i]; }
    if (t == 1023) rp[N_NODES] = sums[1023];
}

__global__ void k_scatter(const int* __restrict__ adj_src, const int* __restrict__ adj_dst,
                          const float* __restrict__ adj_vals,
                          const int* __restrict__ an_dst, const float* __restrict__ an_vals) {
    int e = blockIdx.x * blockDim.x + threadIdx.x;
    if (e >= N_EDGES) return;
    {
        int d = adj_dst[e];
        int p = atomicAdd(&g_cursor_adj[d], 1);
        int idx = g_rp_adj[d] + p;
        g_csr_src[idx] = adj_src[e];
        g_csr_val[idx] = adj_vals[e];
    }
    {
        int d = an_dst[e];
        int p = atomicAdd(&g_cursor_an[d], 1);
        int idx = g_rp_an[d] + p;
        g_csr2_eid[idx] = e;
        g_csr2_val[idx] = an_vals[e];
    }
}

// ---------------- SpMM: one warp per destination row ----------------
template<bool GUARD>
__global__ void k_spmm(const float* __restrict__ dense, float* __restrict__ out) {
    if (GUARD && g_cont == 0) return;
    int w = (blockIdx.x * blockDim.x + threadIdx.x) >> 5;
    int lane = threadIdx.x & 31;
    if (w >= N_NODES) return;
    int i0 = g_rp_adj[w], i1 = g_rp_adj[w + 1];
    float4 acc = make_float4(0.f, 0.f, 0.f, 0.f);
    for (int i = i0; i < i1; i++) {
        int src = g_csr_src[i];
        float v = g_csr_val[i];
        float4 x = *reinterpret_cast<const float4*>(dense + (size_t)src * 128 + lane * 4);
        acc.x += v * x.x; acc.y += v * x.y; acc.z += v * x.z; acc.w += v * x.w;
    }
    *reinterpret_cast<float4*>(out + (size_t)w * 128 + lane * 4) = acc;
}

__global__ void k_agg_arcs(const float* __restrict__ arcs) {
    int w = (blockIdx.x * blockDim.x + threadIdx.x) >> 5;
    int lane = threadIdx.x & 31;
    if (w >= N_NODES) return;
    int i0 = g_rp_an[w], i1 = g_rp_an[w + 1];
    float ax = 0.f, ay = 0.f;
    for (int i = i0; i < i1; i++) {
        int e = g_csr2_eid[i];
        float v = g_csr2_val[i];
        float2 x = *reinterpret_cast<const float2*>(arcs + (size_t)e * 66 + 2 + lane * 2);
        ax += v * x.x; ay += v * x.y;
    }
    float2 o; o.x = ax; o.y = ay;
    *reinterpret_cast<float2*>(g_agga + (size_t)w * 64 + lane * 2) = o;
}

// ---------------- convergence control ----------------
__global__ void k_reset_cont() { g_cont = 0; }
__global__ void k_latch()      { if (g_cont == 0) g_done = 1; }

__global__ void k_dist() {
    if (g_done) return;
    int w = (blockIdx.x * blockDim.x + threadIdx.x) >> 5;
    int lane = threadIdx.x & 31;
    if (w >= N_NODES) return;
    float4 c = *reinterpret_cast<const float4*>(g_cur + (size_t)w * 128 + lane * 4);
    float4 o = *reinterpret_cast<const float4*>(g_old + (size_t)w * 128 + lane * 4);
    float dx = c.x - o.x, dy = c.y - o.y, dz = c.z - o.z, dw = c.w - o.w;
    float d2 = dx * dx + dy * dy + dz * dz + dw * dw;
    float n2 = o.x * o.x + o.y * o.y + o.z * o.z + o.w * o.w;
    #pragma unroll
    for (int off = 16; off > 0; off >>= 1) {
        d2 += __shfl_down_sync(0xffffffffu, d2, off);
        n2 += __shfl_down_sync(0xffffffffu, n2, off);
    }
    if (lane == 0) {
        if (sqrtf(d2) > THRC * sqrtf(n2)) g_cont = 1;
    }
}

// ---------------- tf32 helpers ----------------
__device__ __forceinline__ uint32_t f2tf32(float x) {
    uint32_t u;
    asm("cvt.rna.tf32.f32 %0, %1;" : "=r"(u) : "f"(x));
    return u;
}

__device__ __forceinline__ void mma_tf32(float& d0, float& d1, float& d2, float& d3,
                                         uint32_t a0, uint32_t a1, uint32_t a2, uint32_t a3,
                                         uint32_t b0, uint32_t b1) {
    asm volatile("mma.sync.aligned.m16n8k8.row.col.f32.tf32.tf32.f32 "
                 "{%0,%1,%2,%3}, {%4,%5,%6,%7}, {%8,%9}, {%0,%1,%2,%3};"
                 : "+f"(d0), "+f"(d1), "+f"(d2), "+f"(d3)
                 : "r"(a0), "r"(a1), "r"(a2), "r"(a3), "r"(b0), "r"(b1));
}

// ---------------- GEMM1: tf32 tensor-core, fused 5-way concat + tanh ----------------
// 128x128 tile, 256 threads (8 warps), each warp 64x32 = 4x4 m16n8k8 fragments.
// K-step 8, double-buffered smem; A/B converted to tf32 at staging; fp32 accumulate.
template<bool GUARD>
__global__ void __launch_bounds__(256) k_gemm1_mma(
    const float* __restrict__ A0, const float* __restrict__ A1,
    const float* __restrict__ A2, const float* __restrict__ A3,
    const float* __restrict__ A4,
    const float* __restrict__ B,  const float* __restrict__ bias,
    float* __restrict__ C)
{
    if (GUARD && g_cont == 0) return;
    const int KTOT = 576, NTOT = 512;
    __shared__ uint32_t As[2][8][128];
    __shared__ uint32_t Bs[2][8][132];
    const int tid  = threadIdx.x;
    const int wid  = tid >> 5;
    const int lane = tid & 31;
    const int bm = blockIdx.y, bn = blockIdx.x;
    const int rowA = tid >> 1, kA = (tid & 1) * 4;
    const int kB = tid >> 5, nB = (tid & 31) * 4;

    const int warp_m = (wid & 1) * 64;   // 2 warps over M
    const int warp_n = (wid >> 1) * 32;  // 4 warps over N
    const int grp  = lane >> 2;          // 0..7
    const int thr4 = lane & 3;           // 0..3

    float acc[4][4][4];
    #pragma unroll
    for (int i = 0; i < 4; i++)
        #pragma unroll
        for (int j = 0; j < 4; j++)
            #pragma unroll
            for (int r = 0; r < 4; r++) acc[i][j][r] = 0.f;

    const int mA = bm * 128 + rowA;
    const int KT = KTOT / 8;  // 72

    auto loadA = [&](int kg) -> float4 {
        float4 av = make_float4(0.f, 0.f, 0.f, 0.f);
        if (mA < N_NODES) {
            const int k = kg + kA;
            const float* p;
            if      (k < 128) p = A0 + (size_t)mA * 128 + k;
            else if (k < 256) p = A1 + (size_t)mA * 128 + (k - 128);
            else if (k < 384) p = A2 + (size_t)mA * 128 + (k - 256);
            else if (k < 512) p = A3 + (size_t)mA * 128 + (k - 384);
            else              p = A4 + (size_t)mA * 64  + (k - 512);
            av = *reinterpret_cast<const float4*>(p);
        }
        return av;
    };
    auto loadB = [&](int kg) -> float4 {
        return *reinterpret_cast<const float4*>(B + (size_t)(kg + kB) * NTOT + bn * 128 + nB);
    };
    auto stage = [&](int buf, float4 av, float4 bv) {
        As[buf][kA + 0][rowA] = f2tf32(av.x);
        As[buf][kA + 1][rowA] = f2tf32(av.y);
        As[buf][kA + 2][rowA] = f2tf32(av.z);
        As[buf][kA + 3][rowA] = f2tf32(av.w);
        Bs[buf][kB][nB + 0] = f2tf32(bv.x);
        Bs[buf][kB][nB + 1] = f2tf32(bv.y);
        Bs[buf][kB][nB + 2] = f2tf32(bv.z);
        Bs[buf][kB][nB + 3] = f2tf32(bv.w);
    };

    {
        float4 av = loadA(0), bv = loadB(0);
        stage(0, av, bv);
    }
    __syncthreads();

    for (int kt = 0; kt < KT; kt++) {
        const int cur = kt & 1, nxt = cur ^ 1;
        float4 av, bv;
        if (kt + 1 < KT) { av = loadA((kt + 1) * 8); bv = loadB((kt + 1) * 8); }

        // load fragments
        uint32_t afr[4][4];
        #pragma unroll
        for (int tm = 0; tm < 4; tm++) {
            const int mb = warp_m + tm * 16;
            afr[tm][0] = As[cur][thr4    ][mb + grp];
            afr[tm][1] = As[cur][thr4    ][mb + grp + 8];
            afr[tm][2] = As[cur][thr4 + 4][mb + grp];
            afr[tm][3] = As[cur][thr4 + 4][mb + grp + 8];
        }
        uint32_t bfr[4][2];
        #pragma unroll
        for (int tn = 0; tn < 4; tn++) {
            const int nb = warp_n + tn * 8;
            bfr[tn][0] = Bs[cur][thr4    ][nb + grp];
            bfr[tn][1] = Bs[cur][thr4 + 4][nb + grp];
        }
        #pragma unroll
        for (int tm = 0; tm < 4; tm++)
            #pragma unroll
            for (int tn = 0; tn < 4; tn++)
                mma_tf32(acc[tm][tn][0], acc[tm][tn][1], acc[tm][tn][2], acc[tm][tn][3],
                         afr[tm][0], afr[tm][1], afr[tm][2], afr[tm][3],
                         bfr[tn][0], bfr[tn][1]);

        if (kt + 1 < KT) {
            stage(nxt, av, bv);
            __syncthreads();
        }
    }

    // epilogue: c0,c1 -> (row, 2col), c2,c3 -> (row+8, 2col)
    #pragma unroll
    for (int tm = 0; tm < 4; tm++) {
        const int m0 = bm * 128 + warp_m + tm * 16 + grp;
        #pragma unroll
        for (int tn = 0; tn < 4; tn++) {
            const int n0 = bn * 128 + warp_n + tn * 8 + thr4 * 2;
            const float b0 = bias[n0], b1 = bias[n0 + 1];
            if (m0 < N_NODES) {
                float2 o;
                o.x = tanhf(acc[tm][tn][0] + b0);
                o.y = tanhf(acc[tm][tn][1] + b1);
                *reinterpret_cast<float2*>(C + (size_t)m0 * NTOT + n0) = o;
            }
            if (m0 + 8 < N_NODES) {
                float2 o;
                o.x = tanhf(acc[tm][tn][2] + b0);
                o.y = tanhf(acc[tm][tn][3] + b1);
                *reinterpret_cast<float2*>(C + (size_t)(m0 + 8) * NTOT + n0) = o;
            }
        }
    }
}

// ---------------- double-buffered fp32 SGEMM (GEMM2 + output head) ----------------
// AMODE: 0 = plain A0 (stride KTOT); 2 = concat of 2 (KTOT=256)
// EPI: 0 = plain tanh write; 1 = commit Cold<-C then C<-tanh (NTOT=128 state update)
template<int KTOT, int NTOT, int AMODE, bool GUARD, int EPI>
__global__ void __launch_bounds__(256) k_gemm(
    const float* __restrict__ A0, const float* __restrict__ A1,
    const float* __restrict__ B,  const float* __restrict__ bias,
    float* __restrict__ C, float* __restrict__ Cold)
{
    if (GUARD && g_cont == 0) return;
    __shared__ float As[2][8][128];
    __shared__ float Bs[2][8][132];
    const int tid = threadIdx.x;
    const int tx = tid & 15, ty = tid >> 4;
    const int bm = blockIdx.y, bn = blockIdx.x;
    const int rowA = tid >> 1, kA = (tid & 1) * 4;
    const int kB = tid >> 5, nB = (tid & 31) * 4;

    float acc[8][8];
    #pragma unroll
    for (int i = 0; i < 8; i++)
        #pragma unroll
        for (int j = 0; j < 8; j++) acc[i][j] = 0.f;

    const int mA = bm * 128 + rowA;
    const int KT = KTOT / 8;

    auto loadA = [&](int kg) -> float4 {
        float4 av = make_float4(0.f, 0.f, 0.f, 0.f);
        if (mA < N_NODES) {
            const int k = kg + kA;
            const float* p;
            if (AMODE == 0) {
                p = A0 + (size_t)mA * KTOT + k;
            } else {
                p = (k < 128) ? (A0 + (size_t)mA * 128 + k)
                              : (A1 + (size_t)mA * 128 + (k - 128));
            }
            av = *reinterpret_cast<const float4*>(p);
        }
        return av;
    };
    auto loadB = [&](int kg) -> float4 {
        return *reinterpret_cast<const float4*>(B + (size_t)(kg + kB) * NTOT + bn * 128 + nB);
    };
    auto stage = [&](int buf, float4 av, float4 bv) {
        As[buf][kA + 0][rowA] = av.x;
        As[buf][kA + 1][rowA] = av.y;
        As[buf][kA + 2][rowA] = av.z;
        As[buf][kA + 3][rowA] = av.w;
        *reinterpret_cast<float4*>(&Bs[buf][kB][nB]) = bv;
    };

    {
        float4 av = loadA(0), bv = loadB(0);
        stage(0, av, bv);
    }
    __syncthreads();

    for (int kt = 0; kt < KT; kt++) {
        const int cur = kt & 1, nxt = cur ^ 1;
        float4 av, bv;
        if (kt + 1 < KT) { av = loadA((kt + 1) * 8); bv = loadB((kt + 1) * 8); }

        #pragma unroll
        for (int k = 0; k < 8; k++) {
            float4 a0 = *reinterpret_cast<const float4*>(&As[cur][k][ty * 4]);
            float4 a1 = *reinterpret_cast<const float4*>(&As[cur][k][64 + ty * 4]);
            float4 b0 = *reinterpret_cast<const float4*>(&Bs[cur][k][tx * 4]);
            float4 b1 = *reinterpret_cast<const float4*>(&Bs[cur][k][64 + tx * 4]);
            float a[8] = {a0.x, a0.y, a0.z, a0.w, a1.x, a1.y, a1.z, a1.w};
            float b[8] = {b0.x, b0.y, b0.z, b0.w, b1.x, b1.y, b1.z, b1.w};
            #pragma unroll
            for (int i = 0; i < 8; i++)
                #pragma unroll
                for (int j = 0; j < 8; j++)
                    acc[i][j] += a[i] * b[j];
        }

        if (kt + 1 < KT) {
            stage(nxt, av, bv);
            __syncthreads();
        }
    }

    #pragma unroll
    for (int i = 0; i < 8; i++) {
        int r = (i < 4) ? (ty * 4 + i) : (64 + ty * 4 + (i - 4));
        int m = bm * 128 + r;
        if (m >= N_NODES) continue;
        #pragma unroll
        for (int jh = 0; jh < 2; jh++) {
            int n0 = bn * 128 + jh * 64 + tx * 4;
            float4 o;
            o.x = tanhf(acc[i][jh * 4 + 0] + bias[n0 + 0]);
            o.y = tanhf(acc[i][jh * 4 + 1] + bias[n0 + 1]);
            o.z = tanhf(acc[i][jh * 4 + 2] + bias[n0 + 2]);
            o.w = tanhf(acc[i][jh * 4 + 3] + bias[n0 + 3]);
            if (EPI == 1) {
                float4 cv = *reinterpret_cast<const float4*>(C + (size_t)m * NTOT + n0);
                *reinterpret_cast<float4*>(Cold + (size_t)m * NTOT + n0) = cv;
            }
            *reinterpret_cast<float4*>(C + (size_t)m * NTOT + n0) = o;
        }
    }
}

// ---------------- final projection ----------------
__global__ void k_out(const float* __restrict__ Wo2, const float* __restrict__ bo2,
                      const int* __restrict__ m1, const int* __restrict__ m2,
                      float* __restrict__ out) {
    __shared__ float w[512 * 7];
    int tid = threadIdx.x;
    for (int i = tid; i < 512 * 7; i += 256) w[i] = Wo2[i];
    __syncthreads();
    int warp = tid >> 5, lane = tid & 31;
    int row = blockIdx.x * 8 + warp;
    if (row >= N_NODES) return;
    float acc[7] = {0.f, 0.f, 0.f, 0.f, 0.f, 0.f, 0.f};
    const float* h = g_hidden + (size_t)row * 512;
    for (int k = lane; k < 512; k += 32) {
        float hv = h[k];
        #pragma unroll
        for (int j = 0; j < 7; j++) acc[j] += hv * w[k * 7 + j];
    }
    #pragma unroll
    for (int j = 0; j < 7; j++)
        #pragma unroll
        for (int off = 16; off > 0; off >>= 1)
            acc[j] += __shfl_down_sync(0xffffffffu, acc[j], off);
    if (lane == 0) {
        float msk = (m1[row] != 0 && m2[row] != 0) ? 1.f : 0.f;
        #pragma unroll
        for (int j = 0; j < 7; j++)
            out[(size_t)row * 7 + j] = (acc[j] + bo2[j]) * msk;
    }
}

// ---------------- launcher ----------------
extern "C" void kernel_launch(void* const* d_in, const int* in_sizes, int n_in,
                              void* d_out, int out_size) {
    const float* nodes      = (const float*)d_in[0];
    const float* arcs       = (const float*)d_in[1];
    const int*   smask      = (const int*)d_in[2];
    const int*   omask      = (const int*)d_in[3];
    const int*   adj_src    = (const int*)d_in[4];
    const int*   adj_dst    = (const int*)d_in[5];
    const float* adj_vals   = (const float*)d_in[6];
    const int*   an_dst     = (const int*)d_in[7];
    const float* an_vals    = (const float*)d_in[8];
    const float* state_init = (const float*)d_in[9];
    const float* Ws1        = (const float*)d_in[10];
    const float* bs1        = (const float*)d_in[11];
    const float* Ws2        = (const float*)d_in[12];
    const float* bs2        = (const float*)d_in[13];
    const float* Wo1        = (const float*)d_in[14];
    const float* bo1        = (const float*)d_in[15];
    const float* Wo2        = (const float*)d_in[16];
    const float* bo2        = (const float*)d_in[17];
    float* out = (float*)d_out;

    float *p_cur, *p_old, *p_aggs, *p_aggn, *p_agga, *p_hidden;
    cudaGetSymbolAddress((void**)&p_cur,    g_cur);
    cudaGetSymbolAddress((void**)&p_old,    g_old);
    cudaGetSymbolAddress((void**)&p_aggs,   g_aggs);
    cudaGetSymbolAddress((void**)&p_aggn,   g_aggn);
    cudaGetSymbolAddress((void**)&p_agga,   g_agga);
    cudaGetSymbolAddress((void**)&p_hidden, g_hidden);

    const int MBLK = (N_NODES + 127) / 128;

    k_init<<<(N_NODES * SF + 255) / 256, 256>>>(state_init);
    k_hist<<<(N_EDGES + 255) / 256, 256>>>(adj_dst, an_dst);
    k_scan<<<2, 1024>>>();
    k_scatter<<<(N_EDGES + 255) / 256, 256>>>(adj_src, adj_dst, adj_vals, an_dst, an_vals);
    k_agg_arcs<<<(N_NODES * 32 + 255) / 256, 256>>>(arcs);
    k_spmm<false><<<(N_NODES * 32 + 255) / 256, 256>>>(nodes, p_aggn);

    for (int it = 0; it < MAX_IT; it++) {
        k_reset_cont<<<1, 1>>>();
        k_dist<<<(N_NODES * 32 + 255) / 256, 256>>>();
        k_latch<<<1, 1>>>();
        k_spmm<true><<<(N_NODES * 32 + 255) / 256, 256>>>(p_cur, p_aggs);
        k_gemm1_mma<true><<<dim3(4, MBLK), 256>>>(
            p_cur, nodes, p_aggs, p_aggn, p_agga, Ws1, bs1, p_hidden);
        k_gemm<512, 128, 0, true, 1><<<dim3(1, MBLK), 256>>>(
            p_hidden, nullptr, Ws2, bs2, p_cur, p_old);
    }

    k_gemm<256, 512, 2, false, 0><<<dim3(4, MBLK), 256>>>(
        p_cur, nodes, Wo1, bo1, p_hidden, nullptr);
    k_out<<<(N_NODES + 7) / 8, 256>>>(Wo2, bo2, smask, omask, out);
}